// round 7
// baseline (speedup 1.0000x reference)
#include <cuda_runtime.h>

#define N_NODES 100000
#define D_IN 512
#define DH 20
#define DH2 40
#define D_OUT 128
#define EMAX 3200000

// ---------------- scratch (device globals: no allocs allowed) ----------------
__device__ __align__(16) float g_xt [(size_t)N_NODES * DH2];   // x @ [W1|W2]
__device__ __align__(16) float g_agg[(size_t)N_NODES * DH2];   // init + edge sums
__device__ float g_dinv[N_NODES];
__device__ int   g_deg [N_NODES];
__device__ int   g_cur [N_NODES];
__device__ int   g_off [N_NODES + 1];
__device__ __align__(8) uint2 g_ed[EMAX];    // {src, bits(norm)} per edge, CSR by dst

// ---------------- degree histogram ----------------
__global__ void k_zero() {
    int i = blockIdx.x * blockDim.x + threadIdx.x;
    if (i < N_NODES) { g_deg[i] = 0; g_cur[i] = 0; }
}
__global__ void k_count(const int* __restrict__ dst, int E) {
    int e = blockIdx.x * blockDim.x + threadIdx.x;
    if (e < E) atomicAdd(&g_deg[dst[e]], 1);
}

// ---------------- exclusive scan (1 block, 1024 thr, 2-pass) + dinv ----------
#define SCT 1024
#define SCCH ((N_NODES + SCT - 1) / SCT)   // 98
__global__ __launch_bounds__(SCT) void k_scan() {
    __shared__ int sh[SCT];
    const int t = threadIdx.x;
    const int base = t * SCCH;
    int s = 0;
    for (int i = 0; i < SCCH; i++) {
        int idx = base + i;
        if (idx < N_NODES) s += g_deg[idx];
    }
    sh[t] = s;
    __syncthreads();
    // Hillis-Steele inclusive scan
    for (int o = 1; o < SCT; o <<= 1) {
        int v = (t >= o) ? sh[t - o] : 0;
        __syncthreads();
        sh[t] += v;
        __syncthreads();
    }
    int run = sh[t] - s;   // exclusive prefix of this chunk
    for (int i = 0; i < SCCH; i++) {
        int idx = base + i;
        if (idx < N_NODES) {
            int d = g_deg[idx];
            g_off[idx]  = run;
            g_dinv[idx] = rsqrtf((float)d + 1.0f);
            run += d;
        }
    }
    if (t == SCT - 1) g_off[N_NODES] = sh[SCT - 1];
}

// ---------------- CSR fill: edge -> {src, norm} at slot of dst --------------
__global__ void k_fill(const int* __restrict__ src,
                       const int* __restrict__ dst, int E) {
    int e = blockIdx.x * blockDim.x + threadIdx.x;
    if (e >= E) return;
    int s = src[e];
    int d = dst[e];
    int pos = g_off[d] + atomicAdd(&g_cur[d], 1);
    float nm = g_dinv[s] * g_dinv[d];
    g_ed[pos] = make_uint2((unsigned)s, __float_as_uint(nm));
}

// ---------------- xt = x @ [W1|W2]  (fp32 scalar FMA, smem-tiled) -----------
// 64 threads/CTA, 2 rows/thread -> 128 rows/CTA. K-chunk = 16.
#define GT  64
#define GR  128
#define GKB 16

__global__ __launch_bounds__(GT) void k_gemm(
        const float* __restrict__ x,
        const float* __restrict__ W1, const float* __restrict__ b1,
        const float* __restrict__ W2, const float* __restrict__ b2) {
    __shared__ __align__(16) float xs[GKB][GR + 4];  // transposed x tile
    __shared__ __align__(16) float ws[GKB][DH2];     // weight chunk
    __shared__ __align__(16) float bsm[DH2];

    const int tid  = threadIdx.x;
    const int row0 = blockIdx.x * GR;

    for (int i = tid; i < DH2; i += GT)
        bsm[i] = (i < DH) ? b1[i] : b2[i - DH];

    float acc0[DH2], acc1[DH2];
    #pragma unroll
    for (int c = 0; c < DH2; c++) { acc0[c] = 0.f; acc1[c] = 0.f; }

    for (int kb = 0; kb < D_IN; kb += GKB) {
        __syncthreads();
        // weight chunk: GKB*40 entries
        for (int i = tid; i < GKB * DH2; i += GT) {
            int kk = i / DH2, c = i % DH2;
            ws[kk][c] = (c < DH) ? W1[(size_t)(kb + kk) * DH + c]
                                 : W2[(size_t)(kb + kk) * DH + (c - DH)];
        }
        // x tile: 128 rows x 16 k, transposed into smem
        #pragma unroll
        for (int j = 0; j < GR / GT; j++) {
            int r  = tid + GT * j;
            int gr = row0 + r;
            if (gr < N_NODES) {
                const float4* srcp = (const float4*)(x + (size_t)gr * D_IN + kb);
                #pragma unroll
                for (int q = 0; q < GKB / 4; q++) {
                    float4 v = srcp[q];
                    xs[q*4+0][r] = v.x; xs[q*4+1][r] = v.y;
                    xs[q*4+2][r] = v.z; xs[q*4+3][r] = v.w;
                }
            } else {
                #pragma unroll
                for (int q = 0; q < GKB; q++) xs[q][r] = 0.f;
            }
        }
        __syncthreads();

        #pragma unroll 4
        for (int kk = 0; kk < GKB; kk++) {
            float x0 = xs[kk][tid * 2 + 0];
            float x1 = xs[kk][tid * 2 + 1];
            #pragma unroll
            for (int c = 0; c < DH2; c++) {
                float w = ws[kk][c];
                acc0[c] = fmaf(x0, w, acc0[c]);
                acc1[c] = fmaf(x1, w, acc1[c]);
            }
        }
    }

    // epilogue: write xt and agg-init = xt*dinv^2 + b  (self-loop + bias folded)
    #pragma unroll
    for (int h = 0; h < 2; h++) {
        int row = row0 + tid * 2 + h;
        if (row < N_NODES) {
            float di = g_dinv[row];
            float d2 = di * di;
            float* xo = g_xt  + (size_t)row * DH2;
            float* ao = g_agg + (size_t)row * DH2;
            const float* ac = h ? acc1 : acc0;
            #pragma unroll
            for (int c4 = 0; c4 < DH2 / 4; c4++) {
                float4 vv, va;
                vv.x = ac[c4*4+0]; vv.y = ac[c4*4+1];
                vv.z = ac[c4*4+2]; vv.w = ac[c4*4+3];
                va.x = fmaf(vv.x, d2, bsm[c4*4+0]);
                va.y = fmaf(vv.y, d2, bsm[c4*4+1]);
                va.z = fmaf(vv.z, d2, bsm[c4*4+2]);
                va.w = fmaf(vv.w, d2, bsm[c4*4+3]);
                *(float4*)(xo + c4*4) = vv;
                *(float4*)(ao + c4*4) = va;
            }
        }
    }
}

// ---------------- gather: agg[n] += sum_e xt[src_e] * norm_e ----------------
// 320 threads = 32 nodes x 10 quads. Each (node,quad) owned by ONE thread:
// no atomics. The node's 10 threads run the same edge loop in lockstep ->
// each edge's 160B xt row is read coalesced.
#define GA_NODES 32
__global__ __launch_bounds__(320) void k_gather() {
    const int tid = threadIdx.x;
    const int nl = tid / 10, q = tid % 10;
    const int n = blockIdx.x * GA_NODES + nl;
    if (n >= N_NODES) return;

    const int e0 = g_off[n], e1 = g_off[n + 1];
    float* ap = g_agg + (size_t)n * DH2 + q * 4;
    float4 acc = *(const float4*)ap;

    for (int e = e0; e < e1; e++) {
        uint2 ed = g_ed[e];
        float nm = __uint_as_float(ed.y);
        float4 v = *(const float4*)(g_xt + (size_t)ed.x * DH2 + q * 4);
        acc.x = fmaf(v.x, nm, acc.x);
        acc.y = fmaf(v.y, nm, acc.y);
        acc.z = fmaf(v.z, nm, acc.z);
        acc.w = fmaf(v.w, nm, acc.w);
    }
    *(float4*)ap = acc;
}

// ---------------- m = agg @ Wl + bl ; l2norm ----------------
__global__ __launch_bounds__(128) void k_final(
        const float* __restrict__ Wl1, const float* __restrict__ bl1,
        const float* __restrict__ Wl2, const float* __restrict__ bl2,
        float* __restrict__ out) {
    __shared__ __align__(16) float ws[2 * DH * D_OUT];
    __shared__ __align__(16) float bs[2][D_OUT];
    const int tid = threadIdx.x;

    for (int i = tid; i < DH * D_OUT; i += 128) {
        ws[i]              = Wl1[i];
        ws[DH * D_OUT + i] = Wl2[i];
    }
    bs[0][tid] = bl1[tid];
    bs[1][tid] = bl2[tid];
    __syncthreads();

    int node = blockIdx.x * 128 + tid;
    if (node >= N_NODES) return;
    const float* arow = g_agg + (size_t)node * DH2;

    #pragma unroll 1
    for (int ch = 0; ch < 2; ch++) {
        float4 m[D_OUT / 4];
        #pragma unroll
        for (int j = 0; j < D_OUT / 4; j++) m[j] = *(const float4*)&bs[ch][j*4];

        const float* a   = arow + ch * DH;
        const float* wch = ws + ch * DH * D_OUT;
        #pragma unroll 4
        for (int k = 0; k < DH; k++) {
            float ak = a[k];
            const float* wrow = wch + k * D_OUT;
            #pragma unroll
            for (int j = 0; j < D_OUT / 4; j++) {
                float4 w = *(const float4*)&wrow[j*4];
                m[j].x = fmaf(ak, w.x, m[j].x);
                m[j].y = fmaf(ak, w.y, m[j].y);
                m[j].z = fmaf(ak, w.z, m[j].z);
                m[j].w = fmaf(ak, w.w, m[j].w);
            }
        }
        float ssq = 0.f;
        #pragma unroll
        for (int j = 0; j < D_OUT / 4; j++)
            ssq += m[j].x*m[j].x + m[j].y*m[j].y + m[j].z*m[j].z + m[j].w*m[j].w;
        float inv = 1.0f / fmaxf(sqrtf(ssq), 1e-12f);

        float4* o = (float4*)(out + (size_t)ch * N_NODES * D_OUT + (size_t)node * D_OUT);
        #pragma unroll
        for (int j = 0; j < D_OUT / 4; j++) {
            float4 r = m[j];
            r.x *= inv; r.y *= inv; r.z *= inv; r.w *= inv;
            o[j] = r;
        }
    }
}

// ---------------- launch ----------------
extern "C" void kernel_launch(void* const* d_in, const int* in_sizes, int n_in,
                              void* d_out, int out_size) {
    const float* x   = (const float*)d_in[0];
    const int*   ei  = (const int*)d_in[1];     // int32! (JAX x64 disabled)
    const float* W1  = (const float*)d_in[2];
    const float* b1  = (const float*)d_in[3];
    const float* W2  = (const float*)d_in[4];
    const float* b2  = (const float*)d_in[5];
    const float* Wl1 = (const float*)d_in[6];
    const float* bl1 = (const float*)d_in[7];
    const float* Wl2 = (const float*)d_in[8];
    const float* bl2 = (const float*)d_in[9];
    float* out = (float*)d_out;

    int E = in_sizes[1] / 2;
    if (E > EMAX) E = EMAX;
    const int* srcp = ei;
    const int* dstp = ei + E;

    k_zero  <<<(N_NODES + 255) / 256, 256>>>();
    k_count <<<(E + 255) / 256, 256>>>(dstp, E);
    k_scan  <<<1, SCT>>>();
    k_fill  <<<(E + 255) / 256, 256>>>(srcp, dstp, E);
    k_gemm  <<<(N_NODES + GR - 1) / GR, GT>>>(x, W1, b1, W2, b2);
    k_gather<<<(N_NODES + GA_NODES - 1) / GA_NODES, 320>>>();
    k_final <<<(N_NODES + 127) / 128, 128>>>(Wl1, bl1, Wl2, bl2, out);
}